// round 3
// baseline (speedup 1.0000x reference)
#include <cuda_runtime.h>
#include <cstdint>

#define N_ENTITY 64368
#define N_REL    12
#define DIM      128
#define NB       8
#define N_ITEM   6924
#define EDGES    1000000
#define BATCH    128
#define SEQL     32

// ---------------- device scratch (static, allocation-free) ----------------
__device__ __align__(128) float g_w[(size_t)N_REL * N_ENTITY * DIM];   // ~395 MB
__device__ __align__(128) float g_nodes[(size_t)N_ENTITY * DIM];       // ~33 MB
__device__ __align__(128) float g_u[BATCH * DIM];
__device__ int g_deg[N_ENTITY];
__device__ int g_off[N_ENTITY + 1];
__device__ int g_cursor[N_ENTITY];
__device__ int g_sorted[EDGES];

// ---------------- K1: w[r,n,d] = sum_b att[r,b] * basis[b,n,d] ----------------
__global__ void k_compute_w(const float* __restrict__ basis,
                            const float* __restrict__ att) {
    __shared__ float att_s[N_REL * NB];
    if (threadIdx.x < N_REL * NB) att_s[threadIdx.x] = att[threadIdx.x];
    __syncthreads();

    int tid = blockIdx.x * blockDim.x + threadIdx.x;
    if (tid >= N_ENTITY * (DIM / 4)) return;
    int n = tid >> 5;        // entity
    int c = tid & 31;        // float4 chunk within DIM

    float4 bv[NB];
#pragma unroll
    for (int b = 0; b < NB; b++)
        bv[b] = *(const float4*)(basis + ((size_t)b * N_ENTITY + n) * DIM + c * 4);

#pragma unroll
    for (int r = 0; r < N_REL; r++) {
        float4 o = make_float4(0.f, 0.f, 0.f, 0.f);
#pragma unroll
        for (int b = 0; b < NB; b++) {
            float a = att_s[r * NB + b];
            o.x += a * bv[b].x; o.y += a * bv[b].y;
            o.z += a * bv[b].z; o.w += a * bv[b].w;
        }
        *(float4*)(g_w + ((size_t)r * N_ENTITY + n) * DIM + c * 4) = o;
    }
}

// ---------------- K2: zero degree histogram ----------------
__global__ void k_zero_deg() {
    int i = blockIdx.x * blockDim.x + threadIdx.x;
    if (i < N_ENTITY) g_deg[i] = 0;
}

// ---------------- K3: histogram of dst ----------------
__global__ void k_hist(const int* __restrict__ dst) {
    int e = blockIdx.x * blockDim.x + threadIdx.x;
    if (e < EDGES) atomicAdd(&g_deg[dst[e]], 1);
}

// ---------------- K4: single-block exclusive scan over 64368 bins ----------------
__global__ void k_scan() {
    __shared__ int sh[1024];
    const int CHUNK = (N_ENTITY + 1023) / 1024;   // 63
    int t = threadIdx.x;
    int base = t * CHUNK;

    int s = 0;
    for (int i = 0; i < CHUNK; i++) {
        int idx = base + i;
        if (idx < N_ENTITY) s += g_deg[idx];
    }
    sh[t] = s;
    __syncthreads();
    // Hillis-Steele inclusive scan
    for (int off = 1; off < 1024; off <<= 1) {
        int v = (t >= off) ? sh[t - off] : 0;
        __syncthreads();
        sh[t] += v;
        __syncthreads();
    }
    int run = (t == 0) ? 0 : sh[t - 1];
    for (int i = 0; i < CHUNK; i++) {
        int idx = base + i;
        if (idx < N_ENTITY) {
            g_off[idx] = run;
            g_cursor[idx] = run;
            run += g_deg[idx];
        }
    }
    if (t == 1023) g_off[N_ENTITY] = sh[1023];
}

// ---------------- K5: scatter edges into dst-sorted order ----------------
__global__ void k_scatter(const int* __restrict__ src,
                          const int* __restrict__ dst,
                          const int* __restrict__ type) {
    int e = blockIdx.x * blockDim.x + threadIdx.x;
    if (e < EDGES) {
        int d = dst[e];
        int pos = atomicAdd(&g_cursor[d], 1);
        g_sorted[pos] = src[e] | (type[e] << 20);
    }
}

// ---------------- K6: warp-per-dst aggregation + node update ----------------
__device__ __forceinline__ size_t w_index(int p) {
    int s = p & 0xFFFFF;
    int r = p >> 20;
    return ((size_t)r * N_ENTITY + s) * DIM;
}

__global__ void k_aggr(const float* __restrict__ root,
                       const float* __restrict__ bias) {
    int gw   = (blockIdx.x * blockDim.x + threadIdx.x) >> 5;
    int lane = threadIdx.x & 31;
    if (gw >= N_ENTITY) return;

    int start = g_off[gw];
    int end   = g_off[gw + 1];

    float4 acc = make_float4(0.f, 0.f, 0.f, 0.f);
    int e = start;
    int n4 = end - ((end - start) & 3);
    for (; e < n4; e += 4) {
        int p0 = g_sorted[e + 0], p1 = g_sorted[e + 1];
        int p2 = g_sorted[e + 2], p3 = g_sorted[e + 3];
        float4 v0 = *(const float4*)(g_w + w_index(p0) + lane * 4);
        float4 v1 = *(const float4*)(g_w + w_index(p1) + lane * 4);
        float4 v2 = *(const float4*)(g_w + w_index(p2) + lane * 4);
        float4 v3 = *(const float4*)(g_w + w_index(p3) + lane * 4);
        acc.x += v0.x + v1.x + v2.x + v3.x;
        acc.y += v0.y + v1.y + v2.y + v3.y;
        acc.z += v0.z + v1.z + v2.z + v3.z;
        acc.w += v0.w + v1.w + v2.w + v3.w;
    }
    for (; e < end; e++) {
        int p = g_sorted[e];
        float4 v = *(const float4*)(g_w + w_index(p) + lane * 4);
        acc.x += v.x; acc.y += v.y; acc.z += v.z; acc.w += v.w;
    }

    int deg = end - start;
    float inv = 1.0f / (float)(deg > 0 ? deg : 1);
    float4 r4 = *(const float4*)(root + (size_t)gw * DIM + lane * 4);
    float4 b4 = *(const float4*)(bias + lane * 4);
    float4 o;
    o.x = acc.x * inv + r4.x + b4.x;
    o.y = acc.y * inv + r4.y + b4.y;
    o.z = acc.z * inv + r4.z + b4.z;
    o.w = acc.w * inv + r4.w + b4.w;
    *(float4*)(g_nodes + (size_t)gw * DIM + lane * 4) = o;
}

// ---------------- K7: attention pooling (one block per batch row) ----------------
__global__ void k_pool(const int* __restrict__ seed_ids,
                       const int* __restrict__ seed_len,
                       const float* __restrict__ attn_a,
                       const float* __restrict__ attn_b) {
    __shared__ float h[SEQL][DIM];
    __shared__ float e_sh[SEQL];
    __shared__ float red[4];

    int b = blockIdx.x;
    int d = threadIdx.x;   // 128 threads
    int len = seed_len[b];

    for (int l = 0; l < SEQL; l++) {
        int id = seed_ids[b * SEQL + l];
        h[l][d] = g_nodes[(size_t)id * DIM + d];
    }
    __syncthreads();

    float bd = attn_b[d];
    for (int l = 0; l < SEQL; l++) {
        float t = 0.f;
#pragma unroll 8
        for (int k = 0; k < DIM; k++)
            t += h[l][k] * __ldg(&attn_a[k * DIM + d]);
        float val = tanhf(t) * bd;
#pragma unroll
        for (int o = 16; o > 0; o >>= 1)
            val += __shfl_down_sync(0xffffffff, val, o);
        if ((d & 31) == 0) red[d >> 5] = val;
        __syncthreads();
        if (d == 0) e_sh[l] = red[0] + red[1] + red[2] + red[3];
        __syncthreads();
    }

    float u = 0.f;
    if (len > 0) {
        float m = -1e30f;
        for (int l = 0; l < len; l++) m = fmaxf(m, e_sh[l]);
        float ssum = 0.f;
        for (int l = 0; l < len; l++) ssum += expf(e_sh[l] - m);
        float rinv = 1.f / ssum;
        for (int l = 0; l < len; l++)
            u += expf(e_sh[l] - m) * rinv * h[l][d];
    }
    g_u[b * DIM + d] = u;
}

// ---------------- K8: scores = u @ nodes[:N_ITEM]^T + out_bias ----------------
// dynamic smem: full u (128x128 f32 = 64KB) + padded node tile (32 x 33 float4)
#define SCORES_SMEM (BATCH * DIM * 4 + 32 * 33 * 16)

__global__ void k_scores(const float* __restrict__ out_bias,
                         float* __restrict__ out) {
    extern __shared__ float smem[];
    float4* u_sh4 = (float4*)smem;                        // [128][32] float4
    float4* n_sh4 = (float4*)(smem + BATCH * DIM);        // [32][33] float4 (padded)

    int t  = threadIdx.x;                                  // 256 threads
    int i0 = blockIdx.x * 32;

    // load u (16384 floats = 4096 float4)
    const float4* gu4 = (const float4*)g_u;
    for (int idx = t; idx < BATCH * DIM / 4; idx += 256)
        u_sh4[idx] = gu4[idx];

    // load node tile: rows i0..i0+31, 32 float4 per row, padded stride 33
    const float4* gn4 = (const float4*)g_nodes;
    for (int idx = t; idx < 32 * 32; idx += 256) {
        int r = idx >> 5, c = idx & 31;
        n_sh4[r * 33 + c] = gn4[(size_t)(i0 + r) * 32 + c];   // i0+r < 6944 < N_ENTITY, safe
    }
    __syncthreads();

    int tx = t & 31;     // item within tile
    int ty = t >> 5;     // 0..7, b = ty + 8*j

    float acc[16];
#pragma unroll
    for (int j = 0; j < 16; j++) acc[j] = 0.f;

    for (int d4 = 0; d4 < 32; d4++) {
        float4 nv = n_sh4[tx * 33 + d4];
#pragma unroll
        for (int j = 0; j < 16; j++) {
            float4 uv = u_sh4[(ty + 8 * j) * 32 + d4];
            acc[j] += nv.x * uv.x + nv.y * uv.y + nv.z * uv.z + nv.w * uv.w;
        }
    }

    int i = i0 + tx;
    if (i < N_ITEM) {
        float ob = out_bias[i];
#pragma unroll
        for (int j = 0; j < 16; j++)
            out[(size_t)(ty + 8 * j) * N_ITEM + i] = acc[j] + ob;
    }
}

// ---------------- launch ----------------
extern "C" void kernel_launch(void* const* d_in, const int* in_sizes, int n_in,
                              void* d_out, int out_size) {
    const int*   edge_idx  = (const int*)d_in[0];
    const int*   edge_type = (const int*)d_in[1];
    const int*   seed_ids  = (const int*)d_in[2];
    const int*   seed_len  = (const int*)d_in[3];
    // d_in[4] = labels (unused for scores)
    const float* basis     = (const float*)d_in[5];
    const float* att       = (const float*)d_in[6];
    const float* root      = (const float*)d_in[7];
    const float* rgcn_bias = (const float*)d_in[8];
    const float* attn_a    = (const float*)d_in[9];
    const float* attn_b    = (const float*)d_in[10];
    const float* out_bias  = (const float*)d_in[11];
    float* out = (float*)d_out;

    const int* src = edge_idx;
    const int* dst = edge_idx + EDGES;

    k_compute_w<<<(N_ENTITY * 32 + 255) / 256, 256>>>(basis, att);
    k_zero_deg<<<(N_ENTITY + 255) / 256, 256>>>();
    k_hist<<<(EDGES + 255) / 256, 256>>>(dst);
    k_scan<<<1, 1024>>>();
    k_scatter<<<(EDGES + 255) / 256, 256>>>(src, dst, edge_type);
    k_aggr<<<(N_ENTITY * 32 + 255) / 256, 256>>>(root, rgcn_bias);
    k_pool<<<BATCH, DIM>>>(seed_ids, seed_len, attn_a, attn_b);

    cudaFuncSetAttribute(k_scores, cudaFuncAttributeMaxDynamicSharedMemorySize,
                         SCORES_SMEM);
    k_scores<<<(N_ITEM + 31) / 32, 256, SCORES_SMEM>>>(out_bias, out);
}

// round 4
// speedup vs baseline: 1.5484x; 1.5484x over previous
#include <cuda_runtime.h>
#include <cuda_fp16.h>
#include <cstdint>

#define N_ENTITY 64368
#define N_REL    12
#define DIM      128
#define NB       8
#define N_ITEM   6924
#define EDGES    1000000
#define BATCH    128
#define SEQL     32

#define SCAN_BLOCKS 63   // 63 * 1024 = 64512 >= N_ENTITY

// ---------------- device scratch (static, allocation-free) ----------------
__device__ __align__(128) __half g_w[(size_t)N_REL * N_ENTITY * DIM];  // ~198 MB
__device__ __align__(128) float  g_nodes[(size_t)N_ENTITY * DIM];      // ~33 MB
__device__ __align__(128) float  g_u[BATCH * DIM];
__device__ int g_deg[N_ENTITY];
__device__ int g_off[N_ENTITY + 1];
__device__ int g_cursor[N_ENTITY];
__device__ int g_sorted[EDGES];
__device__ int g_part[SCAN_BLOCKS + 1];

// ---------------- K1: w[r,n,d] = sum_b att[r,b] * basis[b,n,d]  (fp16 out) ----
__global__ void k_compute_w(const float* __restrict__ basis,
                            const float* __restrict__ att) {
    __shared__ float att_s[N_REL * NB];
    if (threadIdx.x < N_REL * NB) att_s[threadIdx.x] = att[threadIdx.x];
    __syncthreads();

    int tid = blockIdx.x * blockDim.x + threadIdx.x;
    if (tid >= N_ENTITY * (DIM / 4)) return;
    int n = tid >> 5;        // entity
    int c = tid & 31;        // float4 chunk within DIM

    float4 bv[NB];
#pragma unroll
    for (int b = 0; b < NB; b++)
        bv[b] = *(const float4*)(basis + ((size_t)b * N_ENTITY + n) * DIM + c * 4);

#pragma unroll
    for (int r = 0; r < N_REL; r++) {
        float4 o = make_float4(0.f, 0.f, 0.f, 0.f);
#pragma unroll
        for (int b = 0; b < NB; b++) {
            float a = att_s[r * NB + b];
            o.x += a * bv[b].x; o.y += a * bv[b].y;
            o.z += a * bv[b].z; o.w += a * bv[b].w;
        }
        __half2 h0 = __floats2half2_rn(o.x, o.y);
        __half2 h1 = __floats2half2_rn(o.z, o.w);
        __half2* p = (__half2*)(g_w + ((size_t)r * N_ENTITY + n) * DIM + c * 4);
        p[0] = h0;
        p[1] = h1;
    }
}

// ---------------- K2: zero degree histogram ----------------
__global__ void k_zero_deg() {
    int i = blockIdx.x * blockDim.x + threadIdx.x;
    if (i < N_ENTITY) g_deg[i] = 0;
}

// ---------------- K3: histogram of dst ----------------
__global__ void k_hist(const int* __restrict__ dst) {
    int e = blockIdx.x * blockDim.x + threadIdx.x;
    if (e < EDGES) atomicAdd(&g_deg[dst[e]], 1);
}

// ---------------- block-wide inclusive scan helper ----------------
__device__ __forceinline__ int block_incl_scan(int v, int t) {
    __shared__ int warp_tot[32];
    int lane = t & 31, wid = t >> 5;
#pragma unroll
    for (int o = 1; o < 32; o <<= 1) {
        int n = __shfl_up_sync(0xffffffffu, v, o);
        if (lane >= o) v += n;
    }
    if (lane == 31) warp_tot[wid] = v;
    __syncthreads();
    if (wid == 0) {
        int w = warp_tot[lane];
#pragma unroll
        for (int o = 1; o < 32; o <<= 1) {
            int n = __shfl_up_sync(0xffffffffu, w, o);
            if (lane >= o) w += n;
        }
        warp_tot[lane] = w;
    }
    __syncthreads();
    if (wid > 0) v += warp_tot[wid - 1];
    return v;
}

// ---------------- K4a: per-block partial sums of deg ----------------
__global__ void k_partial() {
    int idx = blockIdx.x * 1024 + threadIdx.x;
    int v = (idx < N_ENTITY) ? g_deg[idx] : 0;
    int incl = block_incl_scan(v, threadIdx.x);
    if (threadIdx.x == 1023) g_part[blockIdx.x] = incl;
}

// ---------------- K4b: scan 63 partials (tiny) ----------------
__global__ void k_scan_part() {
    int t = threadIdx.x;                 // 64 threads
    int v = (t < SCAN_BLOCKS) ? g_part[t] : 0;
    int incl = block_incl_scan(v, t);
    if (t < SCAN_BLOCKS) g_part[t] = incl - v;   // exclusive
    if (t == 0) g_off[N_ENTITY] = EDGES;
}

// ---------------- K4c: per-block offsets ----------------
__global__ void k_offsets() {
    int idx = blockIdx.x * 1024 + threadIdx.x;
    int v = (idx < N_ENTITY) ? g_deg[idx] : 0;
    int incl = block_incl_scan(v, threadIdx.x);
    int excl = incl - v + g_part[blockIdx.x];
    if (idx < N_ENTITY) {
        g_off[idx]    = excl;
        g_cursor[idx] = excl;
    }
}

// ---------------- K5: scatter edges into dst-sorted order ----------------
__global__ void k_scatter(const int* __restrict__ src,
                          const int* __restrict__ dst,
                          const int* __restrict__ type) {
    int e = blockIdx.x * blockDim.x + threadIdx.x;
    if (e < EDGES) {
        int d = dst[e];
        int pos = atomicAdd(&g_cursor[d], 1);
        g_sorted[pos] = src[e] | (type[e] << 20);
    }
}

// ---------------- K6: warp-per-dst aggregation + node update ----------------
__device__ __forceinline__ size_t w_index(int p) {
    int s = p & 0xFFFFF;
    int r = p >> 20;
    return ((size_t)r * N_ENTITY + s) * DIM;
}

__device__ __forceinline__ void acc_half4(float4& acc, const __half2* p) {
    float2 a = __half22float2(p[0]);
    float2 b = __half22float2(p[1]);
    acc.x += a.x; acc.y += a.y; acc.z += b.x; acc.w += b.y;
}

__global__ void k_aggr(const float* __restrict__ root,
                       const float* __restrict__ bias) {
    int gw   = (blockIdx.x * blockDim.x + threadIdx.x) >> 5;
    int lane = threadIdx.x & 31;
    if (gw >= N_ENTITY) return;

    int start = g_off[gw];
    int end   = g_off[gw + 1];

    float4 acc = make_float4(0.f, 0.f, 0.f, 0.f);
    int e = start;
    int n4 = end - ((end - start) & 3);
    for (; e < n4; e += 4) {
        int p0 = g_sorted[e + 0], p1 = g_sorted[e + 1];
        int p2 = g_sorted[e + 2], p3 = g_sorted[e + 3];
        acc_half4(acc, (const __half2*)(g_w + w_index(p0)) + lane * 2);
        acc_half4(acc, (const __half2*)(g_w + w_index(p1)) + lane * 2);
        acc_half4(acc, (const __half2*)(g_w + w_index(p2)) + lane * 2);
        acc_half4(acc, (const __half2*)(g_w + w_index(p3)) + lane * 2);
    }
    for (; e < end; e++) {
        int p = g_sorted[e];
        acc_half4(acc, (const __half2*)(g_w + w_index(p)) + lane * 2);
    }

    int deg = end - start;
    float inv = 1.0f / (float)(deg > 0 ? deg : 1);
    float4 r4 = *(const float4*)(root + (size_t)gw * DIM + lane * 4);
    float4 b4 = *(const float4*)(bias + lane * 4);
    float4 o;
    o.x = acc.x * inv + r4.x + b4.x;
    o.y = acc.y * inv + r4.y + b4.y;
    o.z = acc.z * inv + r4.z + b4.z;
    o.w = acc.w * inv + r4.w + b4.w;
    *(float4*)(g_nodes + (size_t)gw * DIM + lane * 4) = o;
}

// ---------------- K7: attention pooling (one block per batch row) ----------------
__global__ void k_pool(const int* __restrict__ seed_ids,
                       const int* __restrict__ seed_len,
                       const float* __restrict__ attn_a,
                       const float* __restrict__ attn_b) {
    __shared__ float h[SEQL][DIM];
    __shared__ float e_sh[SEQL];
    __shared__ float red[4];

    int b = blockIdx.x;
    int d = threadIdx.x;   // 128 threads
    int len = seed_len[b];

    for (int l = 0; l < SEQL; l++) {
        int id = seed_ids[b * SEQL + l];
        h[l][d] = g_nodes[(size_t)id * DIM + d];
    }
    __syncthreads();

    float bd = attn_b[d];
    for (int l = 0; l < SEQL; l++) {
        float t = 0.f;
#pragma unroll 8
        for (int k = 0; k < DIM; k++)
            t += h[l][k] * __ldg(&attn_a[k * DIM + d]);
        float val = tanhf(t) * bd;
#pragma unroll
        for (int o = 16; o > 0; o >>= 1)
            val += __shfl_down_sync(0xffffffff, val, o);
        if ((d & 31) == 0) red[d >> 5] = val;
        __syncthreads();
        if (d == 0) e_sh[l] = red[0] + red[1] + red[2] + red[3];
        __syncthreads();
    }

    float u = 0.f;
    if (len > 0) {
        float m = -1e30f;
        for (int l = 0; l < len; l++) m = fmaxf(m, e_sh[l]);
        float ssum = 0.f;
        for (int l = 0; l < len; l++) ssum += expf(e_sh[l] - m);
        float rinv = 1.f / ssum;
        for (int l = 0; l < len; l++)
            u += expf(e_sh[l] - m) * rinv * h[l][d];
    }
    g_u[b * DIM + d] = u;
}

// ---------------- K8: scores = u @ nodes[:N_ITEM]^T + out_bias ----------------
#define SCORES_SMEM (BATCH * DIM * 4 + 32 * 33 * 16)

__global__ void k_scores(const float* __restrict__ out_bias,
                         float* __restrict__ out) {
    extern __shared__ float smem[];
    float4* u_sh4 = (float4*)smem;                        // [128][32] float4
    float4* n_sh4 = (float4*)(smem + BATCH * DIM);        // [32][33] float4 (padded)

    int t  = threadIdx.x;                                  // 256 threads
    int i0 = blockIdx.x * 32;

    const float4* gu4 = (const float4*)g_u;
    for (int idx = t; idx < BATCH * DIM / 4; idx += 256)
        u_sh4[idx] = gu4[idx];

    const float4* gn4 = (const float4*)g_nodes;
    for (int idx = t; idx < 32 * 32; idx += 256) {
        int r = idx >> 5, c = idx & 31;
        n_sh4[r * 33 + c] = gn4[(size_t)(i0 + r) * 32 + c];
    }
    __syncthreads();

    int tx = t & 31;     // item within tile
    int ty = t >> 5;     // 0..7, b = ty + 8*j

    float acc[16];
#pragma unroll
    for (int j = 0; j < 16; j++) acc[j] = 0.f;

    for (int d4 = 0; d4 < 32; d4++) {
        float4 nv = n_sh4[tx * 33 + d4];
#pragma unroll
        for (int j = 0; j < 16; j++) {
            float4 uv = u_sh4[(ty + 8 * j) * 32 + d4];
            acc[j] += nv.x * uv.x + nv.y * uv.y + nv.z * uv.z + nv.w * uv.w;
        }
    }

    int i = i0 + tx;
    if (i < N_ITEM) {
        float ob = out_bias[i];
#pragma unroll
        for (int j = 0; j < 16; j++)
            out[(size_t)(ty + 8 * j) * N_ITEM + i] = acc[j] + ob;
    }
}

// ---------------- launch ----------------
extern "C" void kernel_launch(void* const* d_in, const int* in_sizes, int n_in,
                              void* d_out, int out_size) {
    const int*   edge_idx  = (const int*)d_in[0];
    const int*   edge_type = (const int*)d_in[1];
    const int*   seed_ids  = (const int*)d_in[2];
    const int*   seed_len  = (const int*)d_in[3];
    // d_in[4] = labels (unused for scores)
    const float* basis     = (const float*)d_in[5];
    const float* att       = (const float*)d_in[6];
    const float* root      = (const float*)d_in[7];
    const float* rgcn_bias = (const float*)d_in[8];
    const float* attn_a    = (const float*)d_in[9];
    const float* attn_b    = (const float*)d_in[10];
    const float* out_bias  = (const float*)d_in[11];
    float* out = (float*)d_out;

    const int* src = edge_idx;
    const int* dst = edge_idx + EDGES;

    k_compute_w<<<(N_ENTITY * 32 + 255) / 256, 256>>>(basis, att);
    k_zero_deg<<<(N_ENTITY + 255) / 256, 256>>>();
    k_hist<<<(EDGES + 255) / 256, 256>>>(dst);
    k_partial<<<SCAN_BLOCKS, 1024>>>();
    k_scan_part<<<1, 64>>>();
    k_offsets<<<SCAN_BLOCKS, 1024>>>();
    k_scatter<<<(EDGES + 255) / 256, 256>>>(src, dst, edge_type);
    k_aggr<<<(N_ENTITY * 32 + 255) / 256, 256>>>(root, rgcn_bias);
    k_pool<<<BATCH, DIM>>>(seed_ids, seed_len, attn_a, attn_b);

    cudaFuncSetAttribute(k_scores, cudaFuncAttributeMaxDynamicSharedMemorySize,
                         SCORES_SMEM);
    k_scores<<<(N_ITEM + 31) / 32, 256, SCORES_SMEM>>>(out_bias, out);
}

// round 5
// speedup vs baseline: 1.6054x; 1.0368x over previous
#include <cuda_runtime.h>
#include <cuda_fp16.h>
#include <cstdint>

#define N_ENTITY 64368
#define N_REL    12
#define DIM      128
#define NB       8
#define N_ITEM   6924
#define EDGES    1000000
#define BATCH    128
#define SEQL     32

#define SCAN_BLOCKS 63   // 63 * 1024 = 64512 >= N_ENTITY

// w is built in chunks: chunk t covers entity n=t>>5, float4 col c=t&31, all 12 rels
#define W_CHUNKS      (N_ENTITY * 32)          // 2,059,776
#define W_CHUNKS_H1   1029888                  // = 256 * 4023, first half (done in k_hist)
#define W_CHUNKS_H2   (W_CHUNKS - W_CHUNKS_H1) // 1,029,888 second half (done in k_scatter)
#define FUSED_THREADS 1029888                  // max(EDGES, half-chunks)

// ---------------- device scratch (static, allocation-free) ----------------
__device__ __align__(128) __half g_w[(size_t)N_REL * N_ENTITY * DIM];  // ~198 MB
__device__ __align__(128) float  g_nodes[(size_t)N_ENTITY * DIM];      // ~33 MB
__device__ __align__(128) float  g_u[BATCH * DIM];
__device__ int g_deg[N_ENTITY];
__device__ int g_off[N_ENTITY + 1];
__device__ int g_cursor[N_ENTITY];
__device__ int g_sorted[EDGES];
__device__ int g_part[SCAN_BLOCKS + 1];

// ---------------- w-chunk worker: w[r,n,d] = sum_b att[r,b]*basis[b,n,d] ------
__device__ __forceinline__ void compute_w_chunk(int ch,
                                                const float* __restrict__ basis,
                                                const float* att_s) {
    int n = ch >> 5;        // entity
    int c = ch & 31;        // float4 chunk within DIM

    float4 bv[NB];
#pragma unroll
    for (int b = 0; b < NB; b++)
        bv[b] = *(const float4*)(basis + ((size_t)b * N_ENTITY + n) * DIM + c * 4);

#pragma unroll
    for (int r = 0; r < N_REL; r++) {
        float4 o = make_float4(0.f, 0.f, 0.f, 0.f);
#pragma unroll
        for (int b = 0; b < NB; b++) {
            float a = att_s[r * NB + b];
            o.x += a * bv[b].x; o.y += a * bv[b].y;
            o.z += a * bv[b].z; o.w += a * bv[b].w;
        }
        __half2 h0 = __floats2half2_rn(o.x, o.y);
        __half2 h1 = __floats2half2_rn(o.z, o.w);
        __half2* p = (__half2*)(g_w + ((size_t)r * N_ENTITY + n) * DIM + c * 4);
        p[0] = h0;
        p[1] = h1;
    }
}

// ---------------- K1: zero degree histogram ----------------
__global__ void k_zero_deg() {
    int i = blockIdx.x * blockDim.x + threadIdx.x;
    if (i < N_ENTITY) g_deg[i] = 0;
}

// ---------------- K2: histogram of dst, fused with w-build half 1 ------------
__global__ void k_hist_w(const int* __restrict__ dst,
                         const float* __restrict__ basis,
                         const float* __restrict__ att) {
    __shared__ float att_s[N_REL * NB];
    if (threadIdx.x < N_REL * NB) att_s[threadIdx.x] = att[threadIdx.x];
    __syncthreads();

    int tid = blockIdx.x * blockDim.x + threadIdx.x;
    if (tid < EDGES) atomicAdd(&g_deg[dst[tid]], 1);
    if (tid < W_CHUNKS_H1) compute_w_chunk(tid, basis, att_s);
}

// ---------------- block-wide inclusive scan helper ----------------
__device__ __forceinline__ int block_incl_scan(int v, int t) {
    __shared__ int warp_tot[32];
    int lane = t & 31, wid = t >> 5;
#pragma unroll
    for (int o = 1; o < 32; o <<= 1) {
        int n = __shfl_up_sync(0xffffffffu, v, o);
        if (lane >= o) v += n;
    }
    if (lane == 31) warp_tot[wid] = v;
    __syncthreads();
    if (wid == 0) {
        int w = warp_tot[lane];
#pragma unroll
        for (int o = 1; o < 32; o <<= 1) {
            int n = __shfl_up_sync(0xffffffffu, w, o);
            if (lane >= o) w += n;
        }
        warp_tot[lane] = w;
    }
    __syncthreads();
    if (wid > 0) v += warp_tot[wid - 1];
    return v;
}

// ---------------- K3a: per-block partial sums of deg ----------------
__global__ void k_partial() {
    int idx = blockIdx.x * 1024 + threadIdx.x;
    int v = (idx < N_ENTITY) ? g_deg[idx] : 0;
    int incl = block_incl_scan(v, threadIdx.x);
    if (threadIdx.x == 1023) g_part[blockIdx.x] = incl;
}

// ---------------- K3b: scan 63 partials (tiny) ----------------
__global__ void k_scan_part() {
    int t = threadIdx.x;                 // 64 threads
    int v = (t < SCAN_BLOCKS) ? g_part[t] : 0;
    int incl = block_incl_scan(v, t);
    if (t < SCAN_BLOCKS) g_part[t] = incl - v;   // exclusive
    if (t == 0) g_off[N_ENTITY] = EDGES;
}

// ---------------- K3c: per-block offsets ----------------
__global__ void k_offsets() {
    int idx = blockIdx.x * 1024 + threadIdx.x;
    int v = (idx < N_ENTITY) ? g_deg[idx] : 0;
    int incl = block_incl_scan(v, threadIdx.x);
    int excl = incl - v + g_part[blockIdx.x];
    if (idx < N_ENTITY) {
        g_off[idx]    = excl;
        g_cursor[idx] = excl;
    }
}

// ---------------- K4: scatter edges, fused with w-build half 2 ---------------
__global__ void k_scatter_w(const int* __restrict__ src,
                            const int* __restrict__ dst,
                            const int* __restrict__ type,
                            const float* __restrict__ basis,
                            const float* __restrict__ att) {
    __shared__ float att_s[N_REL * NB];
    if (threadIdx.x < N_REL * NB) att_s[threadIdx.x] = att[threadIdx.x];
    __syncthreads();

    int tid = blockIdx.x * blockDim.x + threadIdx.x;
    if (tid < EDGES) {
        int d = dst[tid];
        int pos = atomicAdd(&g_cursor[d], 1);
        g_sorted[pos] = src[tid] | (type[tid] << 20);
    }
    if (tid < W_CHUNKS_H2) compute_w_chunk(W_CHUNKS_H1 + tid, basis, att_s);
}

// ---------------- K5: warp-per-dst aggregation + node update ----------------
__device__ __forceinline__ size_t w_index(int p) {
    int s = p & 0xFFFFF;
    int r = p >> 20;
    return ((size_t)r * N_ENTITY + s) * DIM;
}

__device__ __forceinline__ void acc_half4(float4& acc, const __half* p) {
    uint2 raw = *(const uint2*)p;   // one 8B load: 4 halves
    __half2 a = *(__half2*)&raw.x;
    __half2 b = *(__half2*)&raw.y;
    float2 fa = __half22float2(a);
    float2 fb = __half22float2(b);
    acc.x += fa.x; acc.y += fa.y; acc.z += fb.x; acc.w += fb.y;
}

__global__ void k_aggr(const float* __restrict__ root,
                       const float* __restrict__ bias) {
    int gw   = (blockIdx.x * blockDim.x + threadIdx.x) >> 5;
    int lane = threadIdx.x & 31;
    if (gw >= N_ENTITY) return;

    int start = g_off[gw];
    int end   = g_off[gw + 1];

    float4 acc = make_float4(0.f, 0.f, 0.f, 0.f);
    int e = start;
    int n4 = end - ((end - start) & 3);
    for (; e < n4; e += 4) {
        int p0 = g_sorted[e + 0], p1 = g_sorted[e + 1];
        int p2 = g_sorted[e + 2], p3 = g_sorted[e + 3];
        acc_half4(acc, g_w + w_index(p0) + lane * 4);
        acc_half4(acc, g_w + w_index(p1) + lane * 4);
        acc_half4(acc, g_w + w_index(p2) + lane * 4);
        acc_half4(acc, g_w + w_index(p3) + lane * 4);
    }
    for (; e < end; e++) {
        int p = g_sorted[e];
        acc_half4(acc, g_w + w_index(p) + lane * 4);
    }

    int deg = end - start;
    float inv = 1.0f / (float)(deg > 0 ? deg : 1);
    float4 r4 = *(const float4*)(root + (size_t)gw * DIM + lane * 4);
    float4 b4 = *(const float4*)(bias + lane * 4);
    float4 o;
    o.x = acc.x * inv + r4.x + b4.x;
    o.y = acc.y * inv + r4.y + b4.y;
    o.z = acc.z * inv + r4.z + b4.z;
    o.w = acc.w * inv + r4.w + b4.w;
    *(float4*)(g_nodes + (size_t)gw * DIM + lane * 4) = o;
}

// ---------------- K6: attention pooling (one block per batch row) ------------
__global__ void k_pool(const int* __restrict__ seed_ids,
                       const int* __restrict__ seed_len,
                       const float* __restrict__ attn_a,
                       const float* __restrict__ attn_b) {
    __shared__ float h[SEQL][DIM];
    __shared__ float e_sh[SEQL];
    __shared__ float red[4];

    int b = blockIdx.x;
    int d = threadIdx.x;   // 128 threads
    int len = seed_len[b];

    for (int l = 0; l < SEQL; l++) {
        int id = seed_ids[b * SEQL + l];
        h[l][d] = g_nodes[(size_t)id * DIM + d];
    }
    __syncthreads();

    float bd = attn_b[d];
    for (int l = 0; l < SEQL; l++) {
        float t = 0.f;
#pragma unroll 8
        for (int k = 0; k < DIM; k++)
            t += h[l][k] * __ldg(&attn_a[k * DIM + d]);
        float val = tanhf(t) * bd;
#pragma unroll
        for (int o = 16; o > 0; o >>= 1)
            val += __shfl_down_sync(0xffffffff, val, o);
        if ((d & 31) == 0) red[d >> 5] = val;
        __syncthreads();
        if (d == 0) e_sh[l] = red[0] + red[1] + red[2] + red[3];
        __syncthreads();
    }

    float u = 0.f;
    if (len > 0) {
        float m = -1e30f;
        for (int l = 0; l < len; l++) m = fmaxf(m, e_sh[l]);
        float ssum = 0.f;
        for (int l = 0; l < len; l++) ssum += expf(e_sh[l] - m);
        float rinv = 1.f / ssum;
        for (int l = 0; l < len; l++)
            u += expf(e_sh[l] - m) * rinv * h[l][d];
    }
    g_u[b * DIM + d] = u;
}

// ---------------- K7: scores = u @ nodes[:N_ITEM]^T + out_bias ---------------
#define SCORES_SMEM (BATCH * DIM * 4 + 32 * 33 * 16)

__global__ void k_scores(const float* __restrict__ out_bias,
                         float* __restrict__ out) {
    extern __shared__ float smem[];
    float4* u_sh4 = (float4*)smem;                        // [128][32] float4
    float4* n_sh4 = (float4*)(smem + BATCH * DIM);        // [32][33] float4 (padded)

    int t  = threadIdx.x;                                  // 256 threads
    int i0 = blockIdx.x * 32;

    const float4* gu4 = (const float4*)g_u;
    for (int idx = t; idx < BATCH * DIM / 4; idx += 256)
        u_sh4[idx] = gu4[idx];

    const float4* gn4 = (const float4*)g_nodes;
    for (int idx = t; idx < 32 * 32; idx += 256) {
        int r = idx >> 5, c = idx & 31;
        n_sh4[r * 33 + c] = gn4[(size_t)(i0 + r) * 32 + c];
    }
    __syncthreads();

    int tx = t & 31;     // item within tile
    int ty = t >> 5;     // 0..7, b = ty + 8*j

    float acc[16];
#pragma unroll
    for (int j = 0; j < 16; j++) acc[j] = 0.f;

    for (int d4 = 0; d4 < 32; d4++) {
        float4 nv = n_sh4[tx * 33 + d4];
#pragma unroll
        for (int j = 0; j < 16; j++) {
            float4 uv = u_sh4[(ty + 8 * j) * 32 + d4];
            acc[j] += nv.x * uv.x + nv.y * uv.y + nv.z * uv.z + nv.w * uv.w;
        }
    }

    int i = i0 + tx;
    if (i < N_ITEM) {
        float ob = out_bias[i];
#pragma unroll
        for (int j = 0; j < 16; j++)
            out[(size_t)(ty + 8 * j) * N_ITEM + i] = acc[j] + ob;
    }
}

// ---------------- launch ----------------
extern "C" void kernel_launch(void* const* d_in, const int* in_sizes, int n_in,
                              void* d_out, int out_size) {
    const int*   edge_idx  = (const int*)d_in[0];
    const int*   edge_type = (const int*)d_in[1];
    const int*   seed_ids  = (const int*)d_in[2];
    const int*   seed_len  = (const int*)d_in[3];
    // d_in[4] = labels (unused for scores)
    const float* basis     = (const float*)d_in[5];
    const float* att       = (const float*)d_in[6];
    const float* root      = (const float*)d_in[7];
    const float* rgcn_bias = (const float*)d_in[8];
    const float* attn_a    = (const float*)d_in[9];
    const float* attn_b    = (const float*)d_in[10];
    const float* out_bias  = (const float*)d_in[11];
    float* out = (float*)d_out;

    const int* src = edge_idx;
    const int* dst = edge_idx + EDGES;

    k_zero_deg<<<(N_ENTITY + 255) / 256, 256>>>();
    k_hist_w<<<FUSED_THREADS / 256, 256>>>(dst, basis, att);
    k_partial<<<SCAN_BLOCKS, 1024>>>();
    k_scan_part<<<1, 64>>>();
    k_offsets<<<SCAN_BLOCKS, 1024>>>();
    k_scatter_w<<<FUSED_THREADS / 256, 256>>>(src, dst, edge_type, basis, att);
    k_aggr<<<(N_ENTITY * 32 + 255) / 256, 256>>>(root, rgcn_bias);
    k_pool<<<BATCH, DIM>>>(seed_ids, seed_len, attn_a, attn_b);

    cudaFuncSetAttribute(k_scores, cudaFuncAttributeMaxDynamicSharedMemorySize,
                         SCORES_SMEM);
    k_scores<<<(N_ITEM + 31) / 32, 256, SCORES_SMEM>>>(out_bias, out);
}